// round 2
// baseline (speedup 1.0000x reference)
#include <cuda_runtime.h>

#define BB  8
#define CC  256
#define PP  64
#define HH  64
#define WW  64
#define HWS 4096   // H*W

// ---------------- scratch (device globals; no allocations allowed) ----------
__device__ __align__(128) float g_top[BB * PP * HWS];        // [B][P][HW]
__device__ __align__(128) float g_centerT[BB * HWS * PP];    // [B][HW][P]
__device__ __align__(128) float g_bottom[BB * HWS * CC];     // [B][HW][C]
__device__ __align__(128) float g_S[134217728];              // [B][HW][HW] 536MB
__device__ __align__(128) float g_attn[BB * HWS * CC];       // [B][HW][C] == reinterpret [B][C][H][W]
__device__ float g_partial[BB * 2048];
__device__ float g_sum[BB];

// ---------------- K1: 1x1 convs (top + centerT fused) -----------------------
// top[b][p][n] = b_top[p] + sum_c Wt[p][c] * x[b][c][n]
// centerT[b][n][p] = b_center[p] + sum_c Wc[p][c] * x[b][c][n]
__global__ void k_top_center(const float* __restrict__ x,
                             const float* __restrict__ wt, const float* __restrict__ bt,
                             const float* __restrict__ wc, const float* __restrict__ bc)
{
    const int b  = blockIdx.y;
    const int n0 = blockIdx.x * 64;
    const int t  = threadIdx.x;
    const int p  = t & 63;
    const int q  = t >> 6;         // 0..3, 16 n's each

    __shared__ float xs[16][64];
    __shared__ float wts[64][17];
    __shared__ float wcs[64][17];

    float acct[16], accc[16];
#pragma unroll
    for (int j = 0; j < 16; j++) { acct[j] = 0.f; accc[j] = 0.f; }

    const float* xb = x + (size_t)b * CC * HWS;

    for (int c0 = 0; c0 < CC; c0 += 16) {
        // load x tile 16c x 64n
        {
            int cc = t >> 4;
            int nn = (t & 15) * 4;
            float4 v = *(const float4*)(xb + (size_t)(c0 + cc) * HWS + n0 + nn);
            *(float4*)&xs[cc][nn] = v;
        }
        // load weight tiles 64p x 16c
        {
            int p_ = t >> 2;
            int cq = (t & 3) * 4;
            float4 v = *(const float4*)(wt + (size_t)p_ * CC + c0 + cq);
            wts[p_][cq + 0] = v.x; wts[p_][cq + 1] = v.y; wts[p_][cq + 2] = v.z; wts[p_][cq + 3] = v.w;
            float4 u = *(const float4*)(wc + (size_t)p_ * CC + c0 + cq);
            wcs[p_][cq + 0] = u.x; wcs[p_][cq + 1] = u.y; wcs[p_][cq + 2] = u.z; wcs[p_][cq + 3] = u.w;
        }
        __syncthreads();
#pragma unroll
        for (int cc = 0; cc < 16; cc++) {
            float at = wts[p][cc];
            float ac = wcs[p][cc];
#pragma unroll
            for (int j = 0; j < 16; j++) {
                float xv = xs[cc][q * 16 + j];
                acct[j] += at * xv;
                accc[j] += ac * xv;
            }
        }
        __syncthreads();
    }

    const float btv = bt[p];
    const float bcv = bc[p];
    float* topp = g_top + ((size_t)b * PP + p) * HWS + n0 + q * 16;
#pragma unroll
    for (int j4 = 0; j4 < 4; j4++) {
        float4 v = make_float4(acct[j4*4+0] + btv, acct[j4*4+1] + btv,
                               acct[j4*4+2] + btv, acct[j4*4+3] + btv);
        *(float4*)(topp + j4 * 4) = v;
    }
    float* cenp = g_centerT + (size_t)b * HWS * PP + (size_t)(n0 + q * 16) * PP + p;
#pragma unroll
    for (int j = 0; j < 16; j++) cenp[(size_t)j * PP] = accc[j] + bcv;
}

// ---------------- K2: 3x3 conv -> bottomT [B][HW][C]  (implicit GEMM) -------
// M = co(256), N = spatial(4096), K = ci*9 (2304)
__global__ void k_conv_bottom(const float* __restrict__ x,
                              const float* __restrict__ w, const float* __restrict__ bias)
{
    const int b  = blockIdx.z;
    const int n0 = blockIdx.x * 128;
    const int m0 = blockIdx.y * 128;
    const int t  = threadIdx.x;
    const int tx = t & 15, ty = t >> 4;

    __shared__ float As[8][128];
    __shared__ float Bs[8][128];

    float acc[8][8];
#pragma unroll
    for (int i = 0; i < 8; i++)
#pragma unroll
        for (int j = 0; j < 8; j++) acc[i][j] = 0.f;

    const float* xb = x + (size_t)b * CC * HWS;

    for (int k0 = 0; k0 < 2304; k0 += 8) {
        // A: weights [256][2304]
        {
            int m  = t >> 1;
            int kq = (t & 1) * 4;
            float4 v = *(const float4*)(w + (size_t)(m0 + m) * 2304 + k0 + kq);
            As[kq + 0][m] = v.x; As[kq + 1][m] = v.y; As[kq + 2][m] = v.z; As[kq + 3][m] = v.w;
        }
        // B: implicit im2col of x
        {
            int kb   = t >> 5;
            int kidx = k0 + kb;
            int ci   = kidx / 9;
            int r    = kidx - ci * 9;
            int dh   = r / 3 - 1;
            int dw   = r - (r / 3) * 3 - 1;
            const float* src = xb + (size_t)ci * HWS;
            int lane = t & 31;
#pragma unroll
            for (int it = 0; it < 4; it++) {
                int n  = n0 + lane + 32 * it;
                int h  = n >> 6, wc_ = n & 63;
                int hh = h + dh, ww = wc_ + dw;
                float v = 0.f;
                if ((unsigned)hh < 64u && (unsigned)ww < 64u) v = src[hh * 64 + ww];
                Bs[kb][lane + 32 * it] = v;
            }
        }
        __syncthreads();
#pragma unroll
        for (int kk = 0; kk < 8; kk++) {
            float a[8], bb_[8];
            *(float4*)(a)     = *(const float4*)&As[kk][ty * 8];
            *(float4*)(a + 4) = *(const float4*)&As[kk][ty * 8 + 4];
            *(float4*)(bb_)     = *(const float4*)&Bs[kk][tx * 8];
            *(float4*)(bb_ + 4) = *(const float4*)&Bs[kk][tx * 8 + 4];
#pragma unroll
            for (int i = 0; i < 8; i++)
#pragma unroll
                for (int j = 0; j < 8; j++) acc[i][j] += a[i] * bb_[j];
        }
        __syncthreads();
    }

    float bcol[8];
#pragma unroll
    for (int i = 0; i < 8; i++) bcol[i] = bias[m0 + ty * 8 + i];

    float* outp = g_bottom + (size_t)b * HWS * CC;
#pragma unroll
    for (int j = 0; j < 8; j++) {
        int n = n0 + tx * 8 + j;
        float4 v0 = make_float4(acc[0][j] + bcol[0], acc[1][j] + bcol[1],
                                acc[2][j] + bcol[2], acc[3][j] + bcol[3]);
        float4 v1 = make_float4(acc[4][j] + bcol[4], acc[5][j] + bcol[5],
                                acc[6][j] + bcol[6], acc[7][j] + bcol[7]);
        *(float4*)(outp + (size_t)n * CC + m0 + ty * 8)     = v0;
        *(float4*)(outp + (size_t)n * CC + m0 + ty * 8 + 4) = v1;
    }
}

// ---------------- K3: S = centerT(4096x64) @ top(64x4096) -------------------
__global__ void k_gemm_S()
{
    const int b  = blockIdx.z;
    const int n0 = blockIdx.x * 128;
    const int m0 = blockIdx.y * 128;
    const int t  = threadIdx.x;
    const int tx = t & 15, ty = t >> 4;

    const float* A  = g_centerT + (size_t)b * HWS * PP + (size_t)m0 * PP;
    const float* Bm = g_top + (size_t)b * PP * HWS + n0;
    float*       Sb = g_S + (size_t)b * HWS * HWS;

    __shared__ float As[8][128];
    __shared__ float Bs[8][128];

    float acc[8][8];
#pragma unroll
    for (int i = 0; i < 8; i++)
#pragma unroll
        for (int j = 0; j < 8; j++) acc[i][j] = 0.f;

    for (int k0 = 0; k0 < PP; k0 += 8) {
        {
            int m  = t >> 1;
            int kq = (t & 1) * 4;
            float4 v = *(const float4*)(A + (size_t)m * PP + k0 + kq);
            As[kq + 0][m] = v.x; As[kq + 1][m] = v.y; As[kq + 2][m] = v.z; As[kq + 3][m] = v.w;
        }
        {
            int kb = t >> 5;
            int nb = (t & 31) * 4;
            *(float4*)&Bs[kb][nb] = *(const float4*)(Bm + (size_t)(k0 + kb) * HWS + nb);
        }
        __syncthreads();
#pragma unroll
        for (int kk = 0; kk < 8; kk++) {
            float a[8], bb_[8];
            *(float4*)(a)       = *(const float4*)&As[kk][ty * 8];
            *(float4*)(a + 4)   = *(const float4*)&As[kk][ty * 8 + 4];
            *(float4*)(bb_)     = *(const float4*)&Bs[kk][tx * 8];
            *(float4*)(bb_ + 4) = *(const float4*)&Bs[kk][tx * 8 + 4];
#pragma unroll
            for (int i = 0; i < 8; i++)
#pragma unroll
                for (int j = 0; j < 8; j++) acc[i][j] += a[i] * bb_[j];
        }
        __syncthreads();
    }

#pragma unroll
    for (int i = 0; i < 8; i++) {
        float* row = Sb + (size_t)(m0 + ty * 8 + i) * HWS + n0 + tx * 8;
        *(float4*)(row)     = make_float4(acc[i][0], acc[i][1], acc[i][2], acc[i][3]);
        *(float4*)(row + 4) = make_float4(acc[i][4], acc[i][5], acc[i][6], acc[i][7]);
    }
}

// ---------------- K4: per-batch sum of exp(S - 40) (deterministic) ----------
__global__ void k_expsum()
{
    const int b   = blockIdx.y;
    const int tid = threadIdx.x;
    size_t base = (size_t)b * HWS * HWS + (size_t)blockIdx.x * 8192 + tid;
    float s = 0.f;
#pragma unroll
    for (int it = 0; it < 32; it++)
        s += __expf(g_S[base + (size_t)it * 256] - 40.f);

    __shared__ float red[256];
    red[tid] = s;
    __syncthreads();
    for (int st = 128; st > 0; st >>= 1) {
        if (tid < st) red[tid] += red[tid + st];
        __syncthreads();
    }
    if (tid == 0) g_partial[b * 2048 + blockIdx.x] = red[0];
}

__global__ void k_expsum2()
{
    const int b   = blockIdx.x;
    const int tid = threadIdx.x;
    float s = 0.f;
    for (int i = tid; i < 2048; i += 256) s += g_partial[b * 2048 + i];
    __shared__ float red[256];
    red[tid] = s;
    __syncthreads();
    for (int st = 128; st > 0; st >>= 1) {
        if (tid < st) red[tid] += red[tid + st];
        __syncthreads();
    }
    if (tid == 0) g_sum[b] = red[0];
}

// ---------------- K5: attn = softmax(S) @ bottom  ([HW x C]) ----------------
// A = exp(S - 40) on the fly; epilogue divides by g_sum[b].
__global__ void k_gemm_attn()
{
    const int b  = blockIdx.z;
    const int n0 = blockIdx.x * 128;   // over C=256
    const int m0 = blockIdx.y * 128;   // over HW
    const int t  = threadIdx.x;
    const int tx = t & 15, ty = t >> 4;

    const float* A  = g_S + (size_t)b * HWS * HWS + (size_t)m0 * HWS;
    const float* Bm = g_bottom + (size_t)b * HWS * CC + n0;

    __shared__ float As[8][128];
    __shared__ float Bs[8][128];

    float acc[8][8];
#pragma unroll
    for (int i = 0; i < 8; i++)
#pragma unroll
        for (int j = 0; j < 8; j++) acc[i][j] = 0.f;

    for (int k0 = 0; k0 < HWS; k0 += 8) {
        {
            int m  = t >> 1;
            int kq = (t & 1) * 4;
            float4 v = *(const float4*)(A + (size_t)m * HWS + k0 + kq);
            As[kq + 0][m] = __expf(v.x - 40.f);
            As[kq + 1][m] = __expf(v.y - 40.f);
            As[kq + 2][m] = __expf(v.z - 40.f);
            As[kq + 3][m] = __expf(v.w - 40.f);
        }
        {
            int kb = t >> 5;
            int nb = (t & 31) * 4;
            *(float4*)&Bs[kb][nb] = *(const float4*)(Bm + (size_t)(k0 + kb) * CC + nb);
        }
        __syncthreads();
#pragma unroll
        for (int kk = 0; kk < 8; kk++) {
            float a[8], bb_[8];
            *(float4*)(a)       = *(const float4*)&As[kk][ty * 8];
            *(float4*)(a + 4)   = *(const float4*)&As[kk][ty * 8 + 4];
            *(float4*)(bb_)     = *(const float4*)&Bs[kk][tx * 8];
            *(float4*)(bb_ + 4) = *(const float4*)&Bs[kk][tx * 8 + 4];
#pragma unroll
            for (int i = 0; i < 8; i++)
#pragma unroll
                for (int j = 0; j < 8; j++) acc[i][j] += a[i] * bb_[j];
        }
        __syncthreads();
    }

    const float inv = 1.0f / g_sum[b];
    float* outp = g_attn + (size_t)b * HWS * CC;
#pragma unroll
    for (int i = 0; i < 8; i++) {
        float* row = outp + (size_t)(m0 + ty * 8 + i) * CC + n0 + tx * 8;
        *(float4*)(row)     = make_float4(acc[i][0] * inv, acc[i][1] * inv, acc[i][2] * inv, acc[i][3] * inv);
        *(float4*)(row + 4) = make_float4(acc[i][4] * inv, acc[i][5] * inv, acc[i][6] * inv, acc[i][7] * inv);
    }
}

// ---------------- K6: out = conv3x3(x + attn_reinterp, w_out) + b_out -------
__global__ void k_conv_out(const float* __restrict__ x,
                           const float* __restrict__ w, const float* __restrict__ bias,
                           float* __restrict__ out)
{
    const int b  = blockIdx.z;
    const int n0 = blockIdx.x * 128;
    const int m0 = blockIdx.y * 128;
    const int t  = threadIdx.x;
    const int tx = t & 15, ty = t >> 4;

    __shared__ float As[8][128];
    __shared__ float Bs[8][128];

    float acc[8][8];
#pragma unroll
    for (int i = 0; i < 8; i++)
#pragma unroll
        for (int j = 0; j < 8; j++) acc[i][j] = 0.f;

    const float* xb = x + (size_t)b * CC * HWS;
    const float* zb = g_attn + (size_t)b * HWS * CC;   // reinterpreted [C][H][W]

    for (int k0 = 0; k0 < 2304; k0 += 8) {
        {
            int m  = t >> 1;
            int kq = (t & 1) * 4;
            float4 v = *(const float4*)(w + (size_t)(m0 + m) * 2304 + k0 + kq);
            As[kq + 0][m] = v.x; As[kq + 1][m] = v.y; As[kq + 2][m] = v.z; As[kq + 3][m] = v.w;
        }
        {
            int kb   = t >> 5;
            int kidx = k0 + kb;
            int ci   = kidx / 9;
            int r    = kidx - ci * 9;
            int dh   = r / 3 - 1;
            int dw   = r - (r / 3) * 3 - 1;
            const float* srcx = xb + (size_t)ci * HWS;
            const float* srcz = zb + (size_t)ci * HWS;
            int lane = t & 31;
#pragma unroll
            for (int it = 0; it < 4; it++) {
                int n  = n0 + lane + 32 * it;
                int h  = n >> 6, wc_ = n & 63;
                int hh = h + dh, ww = wc_ + dw;
                float v = 0.f;
                if ((unsigned)hh < 64u && (unsigned)ww < 64u) {
                    int off = hh * 64 + ww;
                    v = srcx[off] + srcz[off];
                }
                Bs[kb][lane + 32 * it] = v;
            }
        }
        __syncthreads();
#pragma unroll
        for (int kk = 0; kk < 8; kk++) {
            float a[8], bb_[8];
            *(float4*)(a)       = *(const float4*)&As[kk][ty * 8];
            *(float4*)(a + 4)   = *(const float4*)&As[kk][ty * 8 + 4];
            *(float4*)(bb_)     = *(const float4*)&Bs[kk][tx * 8];
            *(float4*)(bb_ + 4) = *(const float4*)&Bs[kk][tx * 8 + 4];
#pragma unroll
            for (int i = 0; i < 8; i++)
#pragma unroll
                for (int j = 0; j < 8; j++) acc[i][j] += a[i] * bb_[j];
        }
        __syncthreads();
    }

#pragma unroll
    for (int i = 0; i < 8; i++) {
        int co = m0 + ty * 8 + i;
        float bv = bias[co];
        float* row = out + (size_t)b * CC * HWS + (size_t)co * HWS + n0 + tx * 8;
        *(float4*)(row)     = make_float4(acc[i][0] + bv, acc[i][1] + bv, acc[i][2] + bv, acc[i][3] + bv);
        *(float4*)(row + 4) = make_float4(acc[i][4] + bv, acc[i][5] + bv, acc[i][6] + bv, acc[i][7] + bv);
    }
}

// ---------------- launch ----------------------------------------------------
extern "C" void kernel_launch(void* const* d_in, const int* in_sizes, int n_in,
                              void* d_out, int out_size)
{
    const float* x  = (const float*)d_in[0];
    const float* wt = (const float*)d_in[1];
    const float* bt = (const float*)d_in[2];
    const float* wc = (const float*)d_in[3];
    const float* bc = (const float*)d_in[4];
    const float* wb = (const float*)d_in[5];
    const float* bbm = (const float*)d_in[6];
    const float* wo = (const float*)d_in[7];
    const float* bo = (const float*)d_in[8];
    float* out = (float*)d_out;

    k_top_center<<<dim3(HWS / 64, BB), 256>>>(x, wt, bt, wc, bc);
    k_conv_bottom<<<dim3(HWS / 128, CC / 128, BB), 256>>>(x, wb, bbm);
    k_gemm_S<<<dim3(HWS / 128, HWS / 128, BB), 256>>>();
    k_expsum<<<dim3(2048, BB), 256>>>();
    k_expsum2<<<BB, 256>>>();
    k_gemm_attn<<<dim3(CC / 128, HWS / 128, BB), 256>>>();
    k_conv_out<<<dim3(HWS / 128, CC / 128, BB), 256>>>(x, wo, bo, out);
}